// round 1
// baseline (speedup 1.0000x reference)
#include <cuda_runtime.h>

// ---------------- scratch (device globals; no runtime alloc) ----------------
__device__ float g_low[4*3*256*256];
__device__ float g_x1[4*8*128*128];
__device__ float g_x2[4*16*64*64];
__device__ float g_x3[4*32*32*32];
__device__ float g_x4[4*64*16*16];
__device__ float g_splat[4*64*256];
__device__ float g_l1[4*128*256];
__device__ float g_l2[4*128*256];
__device__ float g_l3[4*64*256];
__device__ float g_cvec[4*64];
__device__ float g_grid[4*12*8*256];   // [b][cc 12][lb 8][y 16][x 16]

// ---------------- downsample: bilinear 1024->256 (antialias=False) ----------
// out coord maps to input 4o+1.5 -> average of pixels (4o+1, 4o+2)
__global__ void k_down(const float* __restrict__ im) {
    int idx = blockIdx.x * 256 + threadIdx.x;
    if (idx >= 4*3*256*256) return;
    int ox = idx & 255;
    int oy = (idx >> 8) & 255;
    int bc = idx >> 16;
    const float* p = im + (size_t)bc * 1024 * 1024 + (size_t)(4*oy+1) * 1024 + (4*ox+1);
    g_low[idx] = 0.25f * (p[0] + p[1] + p[1024] + p[1025]);
}

// ---------------- 3x3 stride-2 conv, pad 1, relu -----------------------------
template<int CI, int CO, int IHW, int OHW>
__global__ void k_conv(const float* __restrict__ in, const float* __restrict__ w,
                       const float* __restrict__ b, float* __restrict__ out) {
    int idx = blockIdx.x * 256 + threadIdx.x;
    if (idx >= 4*CO*OHW*OHW) return;
    int ox = idx % OHW;
    int oy = (idx / OHW) % OHW;
    int co = (idx / (OHW*OHW)) % CO;
    int bb = idx / (OHW*OHW*CO);
    float acc = b[co];
    const float* inb = in + (size_t)bb * CI * IHW * IHW;
    const float* wc = w + co * CI * 9;
    int iy0 = 2*oy - 1, ix0 = 2*ox - 1;
    #pragma unroll
    for (int ky = 0; ky < 3; ky++) {
        int iy = iy0 + ky;
        if (iy < 0 || iy >= IHW) continue;
        #pragma unroll
        for (int kx = 0; kx < 3; kx++) {
            int ix = ix0 + kx;
            if (ix < 0 || ix >= IHW) continue;
            const float* ip = inb + (size_t)iy * IHW + ix;
            #pragma unroll
            for (int ci = 0; ci < CI; ci++)
                acc = fmaf(ip[(size_t)ci * IHW * IHW], wc[ci*9 + ky*3 + kx], acc);
        }
    }
    out[idx] = fmaxf(acc, 0.f);
}

// ---------------- splat: pw 64->64 + val (NO relu) ---------------------------
__global__ void k_splat(const float* __restrict__ spw, const float* __restrict__ spb,
                        const float* __restrict__ val) {
    int idx = blockIdx.x * 256 + threadIdx.x;   // 65536
    int pos = idx & 255;
    int och = (idx >> 8) & 63;
    int bb  = idx >> 14;
    const float* x = g_x4 + bb * 64 * 256;
    const float* wr = spw + och * 64;
    float acc = spb[och] + val[bb];
    #pragma unroll 8
    for (int i = 0; i < 64; i++) acc = fmaf(wr[i], x[i*256 + pos], acc);
    g_splat[idx] = acc;
}

// ---------------- generic pointwise + relu on 16x16 field --------------------
template<int CI, int CO>
__global__ void k_pw(const float* __restrict__ in, const float* __restrict__ w,
                     const float* __restrict__ b, float* __restrict__ out) {
    int idx = blockIdx.x * 256 + threadIdx.x;
    if (idx >= 4*CO*256) return;
    int pos = idx & 255;
    int och = (idx >> 8) % CO;
    int bb  = idx / (CO * 256);
    const float* x = in + bb * CI * 256;
    const float* wr = w + och * CI;
    float acc = b[och];
    #pragma unroll 8
    for (int i = 0; i < CI; i++) acc = fmaf(wr[i], x[i*256 + pos], acc);
    out[idx] = fmaxf(acc, 0.f);
}

// ---------------- global path: strided pw -> pool -> fc1 -> fc2 --------------
__global__ void k_global(const float* __restrict__ cw, const float* __restrict__ cb,
                         const float* __restrict__ fw1, const float* __restrict__ fb1,
                         const float* __restrict__ fw2, const float* __restrict__ fb2) {
    int bb = blockIdx.x;
    int t = threadIdx.x;  // 64 threads
    __shared__ float c4[4][64];   // [oc][gy*8+gx]
    __shared__ float cp[64];
    __shared__ float f1[64];
    const float* sp = g_splat + bb * 64 * 256;
    int gy = t >> 3, gx = t & 7;
    int pos = (2*gy)*16 + 2*gx;
    for (int oc = 0; oc < 4; oc++) {
        float acc = cb[oc];
        for (int i = 0; i < 64; i++) acc = fmaf(cw[oc*64+i], sp[i*256+pos], acc);
        c4[oc][t] = fmaxf(acc, 0.f);
    }
    __syncthreads();
    {   // 2x2 mean pool, flatten (oc, py, px) -> t
        int oc = t >> 4, py = (t >> 2) & 3, px = t & 3;
        cp[t] = 0.25f * (c4[oc][(2*py)*8 + 2*px]   + c4[oc][(2*py)*8 + 2*px+1] +
                         c4[oc][(2*py+1)*8 + 2*px] + c4[oc][(2*py+1)*8 + 2*px+1]);
    }
    __syncthreads();
    float acc = fb1[t];
    for (int i = 0; i < 64; i++) acc = fmaf(fw1[t*64+i], cp[i], acc);
    f1[t] = fmaxf(acc, 0.f);
    __syncthreads();
    acc = fb2[t];
    for (int i = 0; i < 64; i++) acc = fmaf(fw2[t*64+i], f1[i], acc);
    g_cvec[bb*64 + t] = fmaxf(acc, 0.f);
}

// ---------------- fused = relu(c + loc); coeff = pw 64->96; write grid -------
__global__ void k_coeff(const float* __restrict__ gw, const float* __restrict__ gb) {
    int tile = blockIdx.x;     // 16 tiles of 16 positions
    int bb = blockIdx.y;
    int t = threadIdx.x;       // 256
    __shared__ float fused[64][17];
    const float* l3 = g_l3 + bb * 64 * 256;
    const float* cv = g_cvec + bb * 64;
    for (int k = t; k < 1024; k += 256) {
        int ch = k >> 4, p = k & 15;
        fused[ch][p] = fmaxf(cv[ch] + l3[ch*256 + tile*16 + p], 0.f);
    }
    __syncthreads();
    for (int k = t; k < 1536; k += 256) {
        int och = k >> 4, p = k & 15;
        float acc = gb[och];
        const float* wr = gw + och * 64;
        #pragma unroll 8
        for (int i = 0; i < 64; i++) acc = fmaf(wr[i], fused[i][p], acc);
        int lb = och / 12, cc = och % 12;
        g_grid[((bb*12 + cc)*8 + lb)*256 + tile*16 + p] = acc;
    }
}

// ---------------- fused guide + bilateral slice (full res) -------------------
// 64x64 pixel tile per block; smem caches 3x3 xy-cells * 8 z * 12 ch of grid.
__global__ void __launch_bounds__(256) k_slice(
        const float* __restrict__ im,
        const float* __restrict__ ccm_w, const float* __restrict__ ccm_b,
        const float* __restrict__ shifts, const float* __restrict__ slopes,
        const float* __restrict__ prw, const float* __restrict__ prb,
        float* __restrict__ out) {
    int bx = blockIdx.x, by = blockIdx.y, bb = blockIdx.z;
    __shared__ float sg[3*3*8*12];        // [cell(j*3+k)][z][c], c contiguous
    __shared__ float s_ccm[9], s_ccmb[3], s_sh[48], s_sl[48], s_prw[3], s_prb[1];
    int t = threadIdx.x;

    const float* gr = g_grid + (size_t)bb * 12 * 8 * 256;
    for (int k = t; k < 864; k += 256) {
        int c = k % 12;
        int z = (k / 12) % 8;
        int cell = k / 96;
        int j = cell / 3, kx = cell % 3;
        int yi = min(max(by - 1 + j, 0), 15);
        int xi = min(max(bx - 1 + kx, 0), 15);
        sg[k] = gr[(c*8 + z)*256 + yi*16 + xi];
    }
    if (t < 9)                 s_ccm[t] = ccm_w[t];
    if (t >= 16 && t < 19)     s_ccmb[t-16] = ccm_b[t-16];
    if (t >= 32 && t < 80)     s_sh[t-32] = shifts[t-32];
    if (t >= 96 && t < 144)    s_sl[t-96] = slopes[t-96];
    if (t >= 160 && t < 163)   s_prw[t-160] = prw[t-160];
    if (t == 170)              s_prb[0] = prb[0];
    __syncthreads();

    int x = bx*64 + (t & 63);
    int yb = by*64 + (t >> 6);
    const float* imb = im + (size_t)bb * 3 * 1048576;
    float* outb = out + (size_t)bb * 3 * 1048576;

    float cxv = ((float)x + 0.5f) * (1.0f/64.0f) - 0.5f;
    float x0f = floorf(cxv);
    float wx = cxv - x0f;
    int k0 = (int)x0f - (bx - 1);           // local x cell in {0,1}

    for (int r = 0; r < 16; r++) {
        int y = yb + 4*r;
        float cyv = ((float)y + 0.5f) * (1.0f/64.0f) - 0.5f;
        float y0f = floorf(cyv);
        float wy = cyv - y0f;
        int j0 = (int)y0f - (by - 1);       // local y cell in {0,1}

        size_t poff = (size_t)y * 1024 + x;
        float i0 = imb[poff];
        float i1 = imb[poff + 1048576];
        float i2 = imb[poff + 2097152];

        // guide = clip(pw1(pwl(ccm(im))), 0, 1)
        float g0 = s_ccmb[0] + s_ccm[0]*i0 + s_ccm[1]*i1 + s_ccm[2]*i2;
        float g1 = s_ccmb[1] + s_ccm[3]*i0 + s_ccm[4]*i1 + s_ccm[5]*i2;
        float g2 = s_ccmb[2] + s_ccm[6]*i0 + s_ccm[7]*i1 + s_ccm[8]*i2;
        float t0 = 0.f, t1 = 0.f, t2 = 0.f;
        #pragma unroll
        for (int kk = 0; kk < 16; kk++) {
            t0 = fmaf(s_sl[kk],      fmaxf(g0 - s_sh[kk],      0.f), t0);
            t1 = fmaf(s_sl[16+kk],   fmaxf(g1 - s_sh[16+kk],   0.f), t1);
            t2 = fmaf(s_sl[32+kk],   fmaxf(g2 - s_sh[32+kk],   0.f), t2);
        }
        float gg = s_prb[0] + s_prw[0]*t0 + s_prw[1]*t1 + s_prw[2]*t2;
        float guide = fminf(fmaxf(gg, 0.f), 1.f);

        float cz = guide * 8.0f - 0.5f;
        float z0f = floorf(cz);
        float wz = cz - z0f;
        int z0 = (int)z0f;

        float a0=0,a1=0,a2=0,a3=0,a4=0,a5=0,a6=0,a7=0,a8=0,a9=0,a10=0,a11=0;
        #pragma unroll
        for (int dz = 0; dz < 2; dz++) {
            int zi = min(max(z0 + dz, 0), 7);
            float wzz = dz ? wz : 1.f - wz;
            #pragma unroll
            for (int dy = 0; dy < 2; dy++) {
                int jj = j0 + dy;
                float wyz = wzz * (dy ? wy : 1.f - wy);
                #pragma unroll
                for (int dx = 0; dx < 2; dx++) {
                    int kk2 = k0 + dx;
                    float w = wyz * (dx ? wx : 1.f - wx);
                    const float4* p = (const float4*)&sg[((jj*3 + kk2)*8 + zi)*12];
                    float4 va = p[0], vb = p[1], vc = p[2];
                    a0  = fmaf(w, va.x, a0);  a1  = fmaf(w, va.y, a1);
                    a2  = fmaf(w, va.z, a2);  a3  = fmaf(w, va.w, a3);
                    a4  = fmaf(w, vb.x, a4);  a5  = fmaf(w, vb.y, a5);
                    a6  = fmaf(w, vb.z, a6);  a7  = fmaf(w, vb.w, a7);
                    a8  = fmaf(w, vc.x, a8);  a9  = fmaf(w, vc.y, a9);
                    a10 = fmaf(w, vc.z, a10); a11 = fmaf(w, vc.w, a11);
                }
            }
        }
        outb[poff]           = fmaf(a0, i0, fmaf(a1, i1, fmaf(a2,  i2, a3)));
        outb[poff + 1048576] = fmaf(a4, i0, fmaf(a5, i1, fmaf(a6,  i2, a7)));
        outb[poff + 2097152] = fmaf(a8, i0, fmaf(a9, i1, fmaf(a10, i2, a11)));
    }
}

// ---------------- launcher ---------------------------------------------------
extern "C" void kernel_launch(void* const* d_in, const int* in_sizes, int n_in,
                              void* d_out, int out_size) {
    const float* image = (const float*)d_in[0];
    const float* val   = (const float*)d_in[1];
    const float* sw0 = (const float*)d_in[2];  const float* sb0 = (const float*)d_in[3];
    const float* sw1 = (const float*)d_in[4];  const float* sb1 = (const float*)d_in[5];
    const float* sw2 = (const float*)d_in[6];  const float* sb2 = (const float*)d_in[7];
    const float* sw3 = (const float*)d_in[8];  const float* sb3 = (const float*)d_in[9];
    const float* spw = (const float*)d_in[10]; const float* spb = (const float*)d_in[11];
    const float* lw1 = (const float*)d_in[12]; const float* lb1 = (const float*)d_in[13];
    const float* lw2 = (const float*)d_in[14]; const float* lb2 = (const float*)d_in[15];
    const float* lw3 = (const float*)d_in[16]; const float* lb3 = (const float*)d_in[17];
    const float* cw  = (const float*)d_in[18]; const float* cb  = (const float*)d_in[19];
    const float* fw1 = (const float*)d_in[20]; const float* fb1 = (const float*)d_in[21];
    const float* fw2 = (const float*)d_in[22]; const float* fb2 = (const float*)d_in[23];
    const float* gw  = (const float*)d_in[24]; const float* gb  = (const float*)d_in[25];
    const float* ccm_w = (const float*)d_in[26]; const float* ccm_b = (const float*)d_in[27];
    const float* shifts = (const float*)d_in[28];
    const float* slopes = (const float*)d_in[29];
    const float* prw = (const float*)d_in[30]; const float* prb = (const float*)d_in[31];
    float* out = (float*)d_out;

    float *p_low, *p_x1, *p_x2, *p_x3, *p_x4, *p_splat, *p_l1, *p_l2, *p_l3;
    cudaGetSymbolAddress((void**)&p_low,   g_low);
    cudaGetSymbolAddress((void**)&p_x1,    g_x1);
    cudaGetSymbolAddress((void**)&p_x2,    g_x2);
    cudaGetSymbolAddress((void**)&p_x3,    g_x3);
    cudaGetSymbolAddress((void**)&p_x4,    g_x4);
    cudaGetSymbolAddress((void**)&p_splat, g_splat);
    cudaGetSymbolAddress((void**)&p_l1,    g_l1);
    cudaGetSymbolAddress((void**)&p_l2,    g_l2);
    cudaGetSymbolAddress((void**)&p_l3,    g_l3);

    k_down<<<3072, 256>>>(image);
    k_conv<3, 8, 256, 128><<<2048, 256>>>(p_low, sw0, sb0, p_x1);
    k_conv<8, 16, 128, 64><<<1024, 256>>>(p_x1, sw1, sb1, p_x2);
    k_conv<16, 32, 64, 32><<<512, 256>>>(p_x2, sw2, sb2, p_x3);
    k_conv<32, 64, 32, 16><<<256, 256>>>(p_x3, sw3, sb3, p_x4);
    k_splat<<<256, 256>>>(spw, spb, val);
    k_global<<<4, 64>>>(cw, cb, fw1, fb1, fw2, fb2);
    k_pw<64, 128><<<512, 256>>>(p_splat, lw1, lb1, p_l1);
    k_pw<128, 128><<<512, 256>>>(p_l1, lw2, lb2, p_l2);
    k_pw<128, 64><<<256, 256>>>(p_l2, lw3, lb3, p_l3);
    k_coeff<<<dim3(16, 4), 256>>>(gw, gb);
    k_slice<<<dim3(16, 16, 4), 256>>>(image, ccm_w, ccm_b, shifts, slopes, prw, prb, out);
}